// round 1
// baseline (speedup 1.0000x reference)
#include <cuda_runtime.h>

#define N_NODES 50000
#define N_EDGES 800000
#define IN_DIM 128
#define HID_DIM 256
#define OUT_DIM 64
#define NB_SCAN 49   // ceil(50000/1024)

// ---------------- scratch (device globals: no allocations allowed) ----------
__device__ int   g_cnt[N_NODES];
__device__ int   g_rowptr[N_NODES + 1];
__device__ int   g_cursor[N_NODES];
__device__ int   g_col[N_EDGES];
__device__ int   g_blocksum[NB_SCAN];
__device__ int   g_is64;
__device__ float g_mean[(size_t)N_NODES * IN_DIM];   // 25.6 MB
__device__ float g_h[(size_t)N_NODES * HID_DIM];     // 51.2 MB

// ---------------- f32x2 packed-math helpers (sm_100+ FFMA2 path) -----------
__device__ __forceinline__ unsigned long long fma2(unsigned long long a,
                                                   unsigned long long b,
                                                   unsigned long long c) {
    unsigned long long d;
    asm("fma.rn.f32x2 %0, %1, %2, %3;" : "=l"(d) : "l"(a), "l"(b), "l"(c));
    return d;
}
__device__ __forceinline__ unsigned long long pack2(float lo, float hi) {
    unsigned long long r;
    asm("mov.b64 %0, {%1, %2};" : "=l"(r) : "f"(lo), "f"(hi));
    return r;
}
__device__ __forceinline__ float2 unpack2(unsigned long long v) {
    float2 r;
    asm("mov.b64 {%0, %1}, %2;" : "=f"(r.x), "=f"(r.y) : "l"(v));
    return r;
}

// ---------------- edge index access (int32/int64 agnostic) ------------------
__device__ __forceinline__ int load_edge(const void* ei, int which, int e, int is64) {
    if (is64) return (int)((const long long*)ei)[(size_t)which * N_EDGES + e];
    return ((const int*)ei)[(size_t)which * N_EDGES + e];
}

// Detect whether edge_index was materialized as int64 or int32.
// If int32 data is read as int64, words combine two edge values -> almost
// surely out of [0, N_NODES) for at least one of 64 probes.
__global__ void k_detect(const void* ei) {
    if (threadIdx.x == 0 && blockIdx.x == 0) {
        const long long* p = (const long long*)ei;
        int ok64 = 1;
        for (int i = 0; i < 64; i++) {
            long long v = p[i];
            if (v < 0 || v >= N_NODES) { ok64 = 0; break; }
        }
        g_is64 = ok64;
    }
}

__global__ void k_zero() {
    int i = blockIdx.x * blockDim.x + threadIdx.x;
    if (i < N_NODES) g_cnt[i] = 0;
}

__global__ void k_count(const void* ei) {
    int e = blockIdx.x * blockDim.x + threadIdx.x;
    if (e < N_EDGES) {
        int is64 = g_is64;
        int dst = load_edge(ei, 1, e, is64);
        atomicAdd(&g_cnt[dst], 1);
    }
}

__global__ void k_blocksum() {
    __shared__ int s[1024];
    int i = blockIdx.x * 1024 + threadIdx.x;
    s[threadIdx.x] = (i < N_NODES) ? g_cnt[i] : 0;
    __syncthreads();
    for (int st = 512; st > 0; st >>= 1) {
        if (threadIdx.x < st) s[threadIdx.x] += s[threadIdx.x + st];
        __syncthreads();
    }
    if (threadIdx.x == 0) g_blocksum[blockIdx.x] = s[0];
}

__global__ void k_scanoff() {   // 1 thread: exclusive scan of 49 partials
    int run = 0;
    for (int b = 0; b < NB_SCAN; b++) {
        int v = g_blocksum[b];
        g_blocksum[b] = run;
        run += v;
    }
    g_rowptr[N_NODES] = N_EDGES;
}

__global__ void k_scanfinal() {
    __shared__ int s[1024];
    int tid = threadIdx.x;
    int i = blockIdx.x * 1024 + tid;
    int v = (i < N_NODES) ? g_cnt[i] : 0;
    s[tid] = v;
    __syncthreads();
    for (int st = 1; st < 1024; st <<= 1) {   // inclusive Hillis-Steele
        int t = (tid >= st) ? s[tid - st] : 0;
        __syncthreads();
        s[tid] += t;
        __syncthreads();
    }
    int excl = s[tid] - v + g_blocksum[blockIdx.x];
    if (i < N_NODES) {
        g_rowptr[i] = excl;
        g_cursor[i] = excl;
    }
}

__global__ void k_fill(const void* ei) {
    int e = blockIdx.x * blockDim.x + threadIdx.x;
    if (e < N_EDGES) {
        int is64 = g_is64;
        int src = load_edge(ei, 0, e, is64);
        int dst = load_edge(ei, 1, e, is64);
        int p = atomicAdd(&g_cursor[dst], 1);
        g_col[p] = src;
    }
}

// One warp per node: 32 lanes x float4 = full 128-float row. L2-resident gather.
__global__ void __launch_bounds__(256) k_aggregate(const float* __restrict__ x) {
    int w = (blockIdx.x * blockDim.x + threadIdx.x) >> 5;
    int lane = threadIdx.x & 31;
    if (w >= N_NODES) return;
    int s0 = g_rowptr[w], s1 = g_rowptr[w + 1];
    float4 acc = make_float4(0.f, 0.f, 0.f, 0.f);
    for (int e = s0; e < s1; e += 32) {
        int myc = (e + lane < s1) ? g_col[e + lane] : 0;
        int lim = min(32, s1 - e);
        for (int j = 0; j < lim; j++) {
            int srcn = __shfl_sync(0xffffffffu, myc, j);
            float4 v = *(const float4*)&x[(size_t)srcn * IN_DIM + lane * 4];
            acc.x += v.x; acc.y += v.y; acc.z += v.z; acc.w += v.w;
        }
    }
    int deg = s1 - s0;
    float inv = 1.0f / (float)max(deg, 1);
    float4 m = make_float4(acc.x * inv, acc.y * inv, acc.z * inv, acc.w * inv);
    *(float4*)&g_mean[(size_t)w * IN_DIM + lane * 4] = m;
}

// GEMM1: h = elu( [x | mean] @ [W_r ; W_l] + b_l ),  (50000x256)@(256x256)
// Block tile 64x256, K-tiles of 32, 256 threads, per-thread 4 rows x 16 cols,
// f32x2 packed accumulators (col pairs), a broadcast-packed.
__global__ void __launch_bounds__(256) k_gemm1(const float* __restrict__ x,
                                               const float* __restrict__ Wl,
                                               const float* __restrict__ bl,
                                               const float* __restrict__ Wr) {
    __shared__ __align__(16) float Us[32][65];        // transposed: Us[k][m]
    __shared__ __align__(16) float Ws[32][HID_DIM];
    const int tid = threadIdx.x;
    const int tx = tid & 15;    // col group: cols tx*16 .. tx*16+15
    const int ty = tid >> 4;    // row group: rows ty*4  .. ty*4+3
    const int row0 = blockIdx.x * 64;

    unsigned long long acc[4][8];
#pragma unroll
    for (int r = 0; r < 4; r++)
#pragma unroll
        for (int v = 0; v < 8; v++) acc[r][v] = 0ULL;

    for (int k0 = 0; k0 < 2 * IN_DIM; k0 += 32) {
        const float* Usrc = (k0 < IN_DIM) ? x : g_mean;
        const int koff = k0 & (IN_DIM - 1);
        const float* Wsrc = (k0 < IN_DIM) ? (Wr + (size_t)k0 * HID_DIM)
                                          : (Wl + (size_t)(k0 - IN_DIM) * HID_DIM);
        __syncthreads();
#pragma unroll
        for (int i = 0; i < 2; i++) {           // U tile: 64 rows x 32 k
            int idx = tid + i * 256;
            int m = idx >> 3, g = idx & 7;
            int row = row0 + m;
            float4 v = make_float4(0.f, 0.f, 0.f, 0.f);
            if (row < N_NODES)
                v = *(const float4*)&Usrc[(size_t)row * IN_DIM + koff + g * 4];
            Us[g * 4 + 0][m] = v.x;
            Us[g * 4 + 1][m] = v.y;
            Us[g * 4 + 2][m] = v.z;
            Us[g * 4 + 3][m] = v.w;
        }
#pragma unroll
        for (int i = 0; i < 8; i++) {           // W tile: 32 k x 256 cols
            int idx = tid + i * 256;
            int kk = idx >> 6, jv = idx & 63;
            *(float4*)&Ws[kk][jv * 4] =
                *(const float4*)&Wsrc[(size_t)kk * HID_DIM + jv * 4];
        }
        __syncthreads();
#pragma unroll
        for (int kk = 0; kk < 32; kk++) {
            unsigned long long bp[8];
            const float* wrow = &Ws[kk][tx * 16];
#pragma unroll
            for (int v = 0; v < 4; v++) {
                ulonglong2 t = *(const ulonglong2*)(wrow + v * 4);
                bp[2 * v] = t.x;
                bp[2 * v + 1] = t.y;
            }
#pragma unroll
            for (int r = 0; r < 4; r++) {
                float a = Us[kk][ty * 4 + r];
                unsigned long long ap = pack2(a, a);
#pragma unroll
                for (int v = 0; v < 8; v++)
                    acc[r][v] = fma2(ap, bp[v], acc[r][v]);
            }
        }
    }

    float bv[16];
#pragma unroll
    for (int v = 0; v < 4; v++) {
        float4 b4 = *(const float4*)&bl[tx * 16 + v * 4];
        bv[4 * v + 0] = b4.x; bv[4 * v + 1] = b4.y;
        bv[4 * v + 2] = b4.z; bv[4 * v + 3] = b4.w;
    }
#pragma unroll
    for (int r = 0; r < 4; r++) {
        int row = row0 + ty * 4 + r;
        if (row >= N_NODES) continue;
        float o[16];
#pragma unroll
        for (int v = 0; v < 8; v++) {
            float2 p = unpack2(acc[r][v]);
            o[2 * v + 0] = p.x + bv[2 * v + 0];
            o[2 * v + 1] = p.y + bv[2 * v + 1];
        }
#pragma unroll
        for (int j = 0; j < 16; j++)
            o[j] = (o[j] > 0.f) ? o[j] : expm1f(o[j]);   // ELU (alpha=1)
        float* hp = &g_h[(size_t)row * HID_DIM + tx * 16];
#pragma unroll
        for (int v = 0; v < 4; v++)
            *(float4*)&hp[v * 4] =
                make_float4(o[4 * v], o[4 * v + 1], o[4 * v + 2], o[4 * v + 3]);
    }
}

// GEMM2: out = h @ W_out + b_out   (50000x256)@(256x64)
// Block tile 128x64, K-tiles of 32, per-thread 8 rows x 4 cols,
// f32x2 packed over ROW pairs (a loaded as LDS.64 pairs), b broadcast-packed.
__global__ void __launch_bounds__(256) k_gemm2(const float* __restrict__ Wout,
                                               const float* __restrict__ bout,
                                               float* __restrict__ out) {
    __shared__ __align__(16) float Hs[32][130];       // transposed: Hs[k][m]
    __shared__ __align__(16) float Wo[32][OUT_DIM];
    const int tid = threadIdx.x;
    const int tx = tid & 15;    // cols tx*4 .. tx*4+3
    const int ty = tid >> 4;    // rows ty*8 .. ty*8+7
    const int row0 = blockIdx.x * 128;

    unsigned long long acc[4][4];   // [rowpair][col]
#pragma unroll
    for (int p = 0; p < 4; p++)
#pragma unroll
        for (int c = 0; c < 4; c++) acc[p][c] = 0ULL;

    for (int k0 = 0; k0 < HID_DIM; k0 += 32) {
        __syncthreads();
#pragma unroll
        for (int i = 0; i < 4; i++) {            // H tile: 128 rows x 32 k
            int idx = tid + i * 256;
            int m = idx >> 3, g = idx & 7;
            int row = row0 + m;
            float4 v = make_float4(0.f, 0.f, 0.f, 0.f);
            if (row < N_NODES)
                v = *(const float4*)&g_h[(size_t)row * HID_DIM + k0 + g * 4];
            Hs[g * 4 + 0][m] = v.x;
            Hs[g * 4 + 1][m] = v.y;
            Hs[g * 4 + 2][m] = v.z;
            Hs[g * 4 + 3][m] = v.w;
        }
#pragma unroll
        for (int i = 0; i < 2; i++) {            // Wout tile: 32 k x 64 cols
            int idx = tid + i * 256;
            int kk = idx >> 4, jv = idx & 15;
            *(float4*)&Wo[kk][jv * 4] =
                *(const float4*)&Wout[(size_t)(k0 + kk) * OUT_DIM + jv * 4];
        }
        __syncthreads();
#pragma unroll
        for (int kk = 0; kk < 32; kk++) {
            float4 w = *(const float4*)&Wo[kk][tx * 4];
            unsigned long long bb[4];
            bb[0] = pack2(w.x, w.x);
            bb[1] = pack2(w.y, w.y);
            bb[2] = pack2(w.z, w.z);
            bb[3] = pack2(w.w, w.w);
#pragma unroll
            for (int p = 0; p < 4; p++) {
                unsigned long long ap =
                    *(const unsigned long long*)&Hs[kk][ty * 8 + 2 * p];
#pragma unroll
                for (int c = 0; c < 4; c++)
                    acc[p][c] = fma2(ap, bb[c], acc[p][c]);
            }
        }
    }

    float4 bo = *(const float4*)&bout[tx * 4];
#pragma unroll
    for (int p = 0; p < 4; p++) {
        float2 pc[4];
#pragma unroll
        for (int c = 0; c < 4; c++) pc[c] = unpack2(acc[p][c]);
        int r0 = row0 + ty * 8 + 2 * p;
        if (r0 < N_NODES)
            *(float4*)&out[(size_t)r0 * OUT_DIM + tx * 4] =
                make_float4(pc[0].x + bo.x, pc[1].x + bo.y,
                            pc[2].x + bo.z, pc[3].x + bo.w);
        if (r0 + 1 < N_NODES)
            *(float4*)&out[(size_t)(r0 + 1) * OUT_DIM + tx * 4] =
                make_float4(pc[0].y + bo.x, pc[1].y + bo.y,
                            pc[2].y + bo.z, pc[3].y + bo.w);
    }
}

// ---------------------------------------------------------------------------
extern "C" void kernel_launch(void* const* d_in, const int* in_sizes, int n_in,
                              void* d_out, int out_size) {
    const float* x    = (const float*)d_in[0];
    const void*  ei   = (const void*)d_in[1];
    const float* Wl   = (const float*)d_in[2];
    const float* bl   = (const float*)d_in[3];
    const float* Wr   = (const float*)d_in[4];
    const float* Wout = (const float*)d_in[5];
    const float* bout = (const float*)d_in[6];
    float* out = (float*)d_out;

    k_detect<<<1, 32>>>(ei);
    k_zero<<<(N_NODES + 255) / 256, 256>>>();
    k_count<<<(N_EDGES + 255) / 256, 256>>>(ei);
    k_blocksum<<<NB_SCAN, 1024>>>();
    k_scanoff<<<1, 1>>>();
    k_scanfinal<<<NB_SCAN, 1024>>>();
    k_fill<<<(N_EDGES + 255) / 256, 256>>>(ei);
    k_aggregate<<<(N_NODES * 32 + 255) / 256, 256>>>(x);
    k_gemm1<<<(N_NODES + 63) / 64, 256>>>(x, Wl, bl, Wr);
    k_gemm2<<<(N_NODES + 127) / 128, 256>>>(Wout, bout, out);
}

// round 5
// speedup vs baseline: 2.0610x; 2.0610x over previous
#include <cuda_runtime.h>

#define N_NODES 50000
#define N_EDGES 800000
#define IN_DIM 128
#define HID_DIM 256
#define OUT_DIM 64
#define NB_SCAN 49   // ceil(50000/1024)

// ---------------- scratch (device globals: no allocations allowed) ----------
__device__ int   g_cnt[N_NODES];
__device__ int   g_rowptr[N_NODES + 1];
__device__ int   g_cursor[N_NODES];
__device__ int   g_col[N_EDGES];
__device__ int   g_blocksum[NB_SCAN];
__device__ int   g_is64;
__device__ float g_mean[(size_t)N_NODES * IN_DIM];   // 25.6 MB
__device__ float g_h[(size_t)N_NODES * HID_DIM];     // 51.2 MB

// ---------------- f32x2 packed-math helpers (sm_100+ FFMA2 path) -----------
__device__ __forceinline__ unsigned long long fma2(unsigned long long a,
                                                   unsigned long long b,
                                                   unsigned long long c) {
    unsigned long long d;
    asm("fma.rn.f32x2 %0, %1, %2, %3;" : "=l"(d) : "l"(a), "l"(b), "l"(c));
    return d;
}
__device__ __forceinline__ unsigned long long pack2(float lo, float hi) {
    unsigned long long r;
    asm("mov.b64 %0, {%1, %2};" : "=l"(r) : "f"(lo), "f"(hi));
    return r;
}
__device__ __forceinline__ float2 unpack2(unsigned long long v) {
    float2 r;
    asm("mov.b64 {%0, %1}, %2;" : "=f"(r.x), "=f"(r.y) : "l"(v));
    return r;
}

// ---------------- edge index access (int32/int64 agnostic) ------------------
__device__ __forceinline__ int load_edge(const void* ei, int which, int e, int is64) {
    if (is64) return (int)((const long long*)ei)[(size_t)which * N_EDGES + e];
    return ((const int*)ei)[(size_t)which * N_EDGES + e];
}

// zero counts; thread 0 also detects int64-vs-int32 edge_index encoding.
__global__ void k_zero(const void* ei) {
    int i = blockIdx.x * blockDim.x + threadIdx.x;
    if (i < N_NODES) g_cnt[i] = 0;
    if (i == 0) {
        const long long* p = (const long long*)ei;
        int ok64 = 1;
        for (int j = 0; j < 64; j++) {
            long long v = p[j];
            if (v < 0 || v >= N_NODES) { ok64 = 0; break; }
        }
        g_is64 = ok64;
    }
}

__global__ void k_count(const void* ei) {
    int e = blockIdx.x * blockDim.x + threadIdx.x;
    if (e < N_EDGES) {
        int is64 = g_is64;
        int dst = load_edge(ei, 1, e, is64);
        atomicAdd(&g_cnt[dst], 1);
    }
}

__global__ void k_blocksum() {
    __shared__ int s[1024];
    int i = blockIdx.x * 1024 + threadIdx.x;
    s[threadIdx.x] = (i < N_NODES) ? g_cnt[i] : 0;
    __syncthreads();
    for (int st = 512; st > 0; st >>= 1) {
        if (threadIdx.x < st) s[threadIdx.x] += s[threadIdx.x + st];
        __syncthreads();
    }
    if (threadIdx.x == 0) g_blocksum[blockIdx.x] = s[0];
}

__global__ void k_scanoff() {   // 1 thread: exclusive scan of 49 partials
    int run = 0;
    for (int b = 0; b < NB_SCAN; b++) {
        int v = g_blocksum[b];
        g_blocksum[b] = run;
        run += v;
    }
    g_rowptr[N_NODES] = N_EDGES;
}

__global__ void k_scanfinal() {
    __shared__ int s[1024];
    int tid = threadIdx.x;
    int i = blockIdx.x * 1024 + tid;
    int v = (i < N_NODES) ? g_cnt[i] : 0;
    s[tid] = v;
    __syncthreads();
    for (int st = 1; st < 1024; st <<= 1) {   // inclusive Hillis-Steele
        int t = (tid >= st) ? s[tid - st] : 0;
        __syncthreads();
        s[tid] += t;
        __syncthreads();
    }
    int excl = s[tid] - v + g_blocksum[blockIdx.x];
    if (i < N_NODES) {
        g_rowptr[i] = excl;
        g_cursor[i] = excl;
    }
}

__global__ void k_fill(const void* ei) {
    int e = blockIdx.x * blockDim.x + threadIdx.x;
    if (e < N_EDGES) {
        int is64 = g_is64;
        int src = load_edge(ei, 0, e, is64);
        int dst = load_edge(ei, 1, e, is64);
        int p = atomicAdd(&g_cursor[dst], 1);
        g_col[p] = src;
    }
}

// One warp per node: 32 lanes x float4 = full 128-float row. L2-resident gather.
__global__ void __launch_bounds__(256) k_aggregate(const float* __restrict__ x) {
    int w = (blockIdx.x * blockDim.x + threadIdx.x) >> 5;
    int lane = threadIdx.x & 31;
    if (w >= N_NODES) return;
    int s0 = g_rowptr[w], s1 = g_rowptr[w + 1];
    float4 acc = make_float4(0.f, 0.f, 0.f, 0.f);
    for (int e = s0; e < s1; e += 32) {
        int myc = (e + lane < s1) ? g_col[e + lane] : 0;
        int lim = min(32, s1 - e);
        for (int j = 0; j < lim; j++) {
            int srcn = __shfl_sync(0xffffffffu, myc, j);
            float4 v = *(const float4*)&x[(size_t)srcn * IN_DIM + lane * 4];
            acc.x += v.x; acc.y += v.y; acc.z += v.z; acc.w += v.w;
        }
    }
    int deg = s1 - s0;
    float inv = 1.0f / (float)max(deg, 1);
    float4 m = make_float4(acc.x * inv, acc.y * inv, acc.z * inv, acc.w * inv);
    *(float4*)&g_mean[(size_t)w * IN_DIM + lane * 4] = m;
}

// ---------------------------------------------------------------------------
// GEMM1: h = elu( [x | mean] @ [W_r ; W_l] + b_l ),  (50000x256)@(256x256)
// Block tile 128x128, K-tiles of 32, 256 threads, per-thread 8 rows x 8 cols.
// Columns per thread: tx*4 + v*64 (v=0,1) -> conflict-free LDS.128 on B.
// A tile stored k-major (transposed) -> 2 broadcast LDS.128 per kk.
// f32x2 packed accumulators over column pairs; A broadcast-packed.
__global__ void __launch_bounds__(256, 2) k_gemm1(const float* __restrict__ x,
                                                  const float* __restrict__ Wl,
                                                  const float* __restrict__ bl,
                                                  const float* __restrict__ Wr) {
    __shared__ __align__(16) float Us[32][132];       // k-major: Us[k][m]
    __shared__ __align__(16) float Ws[32][128];       // Ws[k][n]
    const int tid = threadIdx.x;
    const int tx = tid & 15;        // col group
    const int ty = tid >> 4;        // rows ty*8 .. ty*8+7
    const int rb = blockIdx.x >> 1;
    const int cb = blockIdx.x & 1;
    const int row0 = rb * 128;
    const int col0 = cb * 128;

    unsigned long long acc[8][4];
#pragma unroll
    for (int r = 0; r < 8; r++)
#pragma unroll
        for (int v = 0; v < 4; v++) acc[r][v] = 0ULL;

    for (int k0 = 0; k0 < 2 * IN_DIM; k0 += 32) {
        const float* Usrc = (k0 < IN_DIM) ? x : g_mean;
        const int koff = k0 & (IN_DIM - 1);
        const float* Wsrc = ((k0 < IN_DIM) ? (Wr + (size_t)k0 * HID_DIM)
                                           : (Wl + (size_t)(k0 - IN_DIM) * HID_DIM)) + col0;
        __syncthreads();
        // U tile: 128 rows x 32 k  (coalesced LDG, transposed STS)
#pragma unroll
        for (int i = 0; i < 4; i++) {
            int idx = tid + i * 256;
            int m = idx >> 3, g = idx & 7;
            int row = row0 + m;
            float4 v = make_float4(0.f, 0.f, 0.f, 0.f);
            if (row < N_NODES)
                v = *(const float4*)&Usrc[(size_t)row * IN_DIM + koff + g * 4];
            Us[g * 4 + 0][m] = v.x;
            Us[g * 4 + 1][m] = v.y;
            Us[g * 4 + 2][m] = v.z;
            Us[g * 4 + 3][m] = v.w;
        }
        // W tile: 32 k x 128 cols (fully coalesced)
#pragma unroll
        for (int i = 0; i < 4; i++) {
            int idx = tid + i * 256;
            int kk = idx >> 5, jv = idx & 31;
            *(float4*)&Ws[kk][jv * 4] =
                *(const float4*)&Wsrc[(size_t)kk * HID_DIM + jv * 4];
        }
        __syncthreads();
#pragma unroll
        for (int kk = 0; kk < 32; kk++) {
            ulonglong2 t0 = *(const ulonglong2*)&Ws[kk][tx * 4];
            ulonglong2 t1 = *(const ulonglong2*)&Ws[kk][64 + tx * 4];
            unsigned long long bp[4] = {t0.x, t0.y, t1.x, t1.y};
            float4 a0 = *(const float4*)&Us[kk][ty * 8];
            float4 a1 = *(const float4*)&Us[kk][ty * 8 + 4];
            unsigned long long ap[8];
            ap[0] = pack2(a0.x, a0.x); ap[1] = pack2(a0.y, a0.y);
            ap[2] = pack2(a0.z, a0.z); ap[3] = pack2(a0.w, a0.w);
            ap[4] = pack2(a1.x, a1.x); ap[5] = pack2(a1.y, a1.y);
            ap[6] = pack2(a1.z, a1.z); ap[7] = pack2(a1.w, a1.w);
#pragma unroll
            for (int r = 0; r < 8; r++)
#pragma unroll
                for (int v = 0; v < 4; v++)
                    acc[r][v] = fma2(ap[r], bp[v], acc[r][v]);
        }
    }

    float4 b0 = *(const float4*)&bl[col0 + tx * 4];
    float4 b1 = *(const float4*)&bl[col0 + 64 + tx * 4];
    const float bv[8] = {b0.x, b0.y, b0.z, b0.w, b1.x, b1.y, b1.z, b1.w};
#pragma unroll
    for (int r = 0; r < 8; r++) {
        int row = row0 + ty * 8 + r;
        if (row >= N_NODES) continue;
        float o[8];
#pragma unroll
        for (int v = 0; v < 4; v++) {
            float2 p = unpack2(acc[r][v]);
            o[2 * v + 0] = p.x + bv[2 * v + 0];
            o[2 * v + 1] = p.y + bv[2 * v + 1];
        }
#pragma unroll
        for (int j = 0; j < 8; j++)
            o[j] = (o[j] > 0.f) ? o[j] : expm1f(o[j]);   // ELU (alpha=1)
        float* hp = &g_h[(size_t)row * HID_DIM + col0];
        *(float4*)&hp[tx * 4]      = make_float4(o[0], o[1], o[2], o[3]);
        *(float4*)&hp[64 + tx * 4] = make_float4(o[4], o[5], o[6], o[7]);
    }
}

// ---------------------------------------------------------------------------
// GEMM2: out = h @ W_out + b_out   (50000x256)@(256x64)
// Block tile 128x64, 128 threads, per-thread 8 rows x 8 cols (tx*4 + v*32).
__global__ void __launch_bounds__(128, 4) k_gemm2(const float* __restrict__ Wout,
                                                  const float* __restrict__ bout,
                                                  float* __restrict__ out) {
    __shared__ __align__(16) float Hs[32][132];       // k-major: Hs[k][m]
    __shared__ __align__(16) float Wo[32][64];
    const int tid = threadIdx.x;
    const int tx = tid & 7;         // cols tx*4 + v*32
    const int ty = tid >> 3;        // rows ty*8 .. ty*8+7
    const int row0 = blockIdx.x * 128;

    unsigned long long acc[8][4];
#pragma unroll
    for (int r = 0; r < 8; r++)
#pragma unroll
        for (int v = 0; v < 4; v++) acc[r][v] = 0ULL;

    for (int k0 = 0; k0 < HID_DIM; k0 += 32) {
        __syncthreads();
        // H tile: 128 rows x 32 k
#pragma unroll
        for (int i = 0; i < 8; i++) {
            int idx = tid + i * 128;
            int m = idx >> 3, g = idx & 7;
            int row = row0 + m;
            float4 v = make_float4(0.f, 0.f, 0.f, 0.f);
            if (row < N_NODES)
                v = *(const float4*)&g_h[(size_t)row * HID_DIM + k0 + g * 4];
            Hs[g * 4 + 0][m] = v.x;
            Hs[g * 4 + 1][m] = v.y;
            Hs[g * 4 + 2][m] = v.z;
            Hs[g * 4 + 3][m] = v.w;
        }
        // Wout tile: 32 k x 64 cols
#pragma unroll
        for (int i = 0; i < 4; i++) {
            int idx = tid + i * 128;
            int kk = idx >> 4, jv = idx & 15;
            *(float4*)&Wo[kk][jv * 4] =
                *(const float4*)&Wout[(size_t)(k0 + kk) * OUT_DIM + jv * 4];
        }
        __syncthreads();
#pragma unroll
        for (int kk = 0; kk < 32; kk++) {
            ulonglong2 t0 = *(const ulonglong2*)&Wo[kk][tx * 4];
            ulonglong2 t1 = *(const ulonglong2*)&Wo[kk][32 + tx * 4];
            unsigned long long bp[4] = {t0.x, t0.y, t1.x, t1.y};
            float4 a0 = *(const float4*)&Hs[kk][ty * 8];
            float4 a1 = *(const float4*)&Hs[kk][ty * 8 + 4];
            unsigned long long ap[8];
            ap[0] = pack2(a0.x, a0.x); ap[1] = pack2(a0.y, a0.y);
            ap[2] = pack2(a0.z, a0.z); ap[3] = pack2(a0.w, a0.w);
            ap[4] = pack2(a1.x, a1.x); ap[5] = pack2(a1.y, a1.y);
            ap[6] = pack2(a1.z, a1.z); ap[7] = pack2(a1.w, a1.w);
#pragma unroll
            for (int r = 0; r < 8; r++)
#pragma unroll
                for (int v = 0; v < 4; v++)
                    acc[r][v] = fma2(ap[r], bp[v], acc[r][v]);
        }
    }

    float4 b0 = *(const float4*)&bout[tx * 4];
    float4 b1 = *(const float4*)&bout[32 + tx * 4];
    const float bv[8] = {b0.x, b0.y, b0.z, b0.w, b1.x, b1.y, b1.z, b1.w};
#pragma unroll
    for (int r = 0; r < 8; r++) {
        int row = row0 + ty * 8 + r;
        if (row >= N_NODES) continue;
        float o[8];
#pragma unroll
        for (int v = 0; v < 4; v++) {
            float2 p = unpack2(acc[r][v]);
            o[2 * v + 0] = p.x + bv[2 * v + 0];
            o[2 * v + 1] = p.y + bv[2 * v + 1];
        }
        float* op = &out[(size_t)row * OUT_DIM];
        *(float4*)&op[tx * 4]      = make_float4(o[0], o[1], o[2], o[3]);
        *(float4*)&op[32 + tx * 4] = make_float4(o[4], o[5], o[6], o[7]);
    }
}

// ---------------------------------------------------------------------------
extern "C" void kernel_launch(void* const* d_in, const int* in_sizes, int n_in,
                              void* d_out, int out_size) {
    const float* x    = (const float*)d_in[0];
    const void*  ei   = (const void*)d_in[1];
    const float* Wl   = (const float*)d_in[2];
    const float* bl   = (const float*)d_in[3];
    const float* Wr   = (const float*)d_in[4];
    const float* Wout = (const float*)d_in[5];
    const float* bout = (const float*)d_in[6];
    float* out = (float*)d_out;

    k_zero<<<(N_NODES + 255) / 256, 256>>>(ei);
    k_count<<<(N_EDGES + 255) / 256, 256>>>(ei);
    k_blocksum<<<NB_SCAN, 1024>>>();
    k_scanoff<<<1, 1>>>();
    k_scanfinal<<<NB_SCAN, 1024>>>();
    k_fill<<<(N_EDGES + 255) / 256, 256>>>(ei);
    k_aggregate<<<(N_NODES * 32 + 255) / 256, 256>>>(x);
    k_gemm1<<<((N_NODES + 127) / 128) * 2, 256>>>(x, Wl, bl, Wr);
    k_gemm2<<<(N_NODES + 127) / 128, 128>>>(Wout, bout, out);
}